// round 1
// baseline (speedup 1.0000x reference)
#include <cuda_runtime.h>
#include <math.h>

// Problem constants
#define Dd 32
#define Hh 1024
#define Ll 2
#define Bb 4096

// ---------------- device scratch (static, no allocation) ----------------
__device__ float g_pre0[Bb * Hh];          // layer-0 pre-activations, maintained incrementally
__device__ float g_a1[Bb * Hh];            // hidden layer 1 output (post-relu)
__device__ float g_a2[Bb * Hh];            // hidden layer 2 output (post-relu)
__device__ float g_Whs[Ll * Hh * Hh];      // masked, degree-sorted hidden weights
__device__ float g_bhs[Ll * Hh];           // permuted hidden biases
__device__ float g_W0sT[Dd * Hh];          // masked, sorted W0, TRANSPOSED: [D][H]
__device__ float g_Wos[2 * Dd * Hh];       // masked output weights, sorted cols

// Degree-sorted permutation. Hidden degree of original unit i is i % 31.
// Sorted index s -> original index P(s); degree of sorted unit s is G(s).
// Group 0 has 34 units (0,31,...,1023); groups 1..30 have 33 units each.
__device__ __forceinline__ int permS(int s) {
    return (s < 34) ? 31 * s : ((s - 1) / 33) + 31 * ((s - 1) % 33);
}
__device__ __forceinline__ int degS(int s) {
    return (s < 34) ? 0 : (s - 1) / 33;
}

// prefix size at step idx: number of hidden units with degree <= idx-1
static inline int prefixH(int idx) { return (idx == 0) ? 0 : (33 * idx + 1); }

// ---------------- weight pre-transform (masked + degree-sorted) ----------------
__global__ void prep_kernel(const float* __restrict__ W0,
                            const float* __restrict__ Wh,
                            const float* __restrict__ bh,
                            const float* __restrict__ Wout) {
    int stride = gridDim.x * blockDim.x;
    int tid0 = blockIdx.x * blockDim.x + threadIdx.x;

    // hidden weights: Whs[l][s][t] = mh * Wh, sorted both dims (block lower-triangular)
    for (int i = tid0; i < Ll * Hh * Hh; i += stride) {
        int l = i >> 20;
        int rem = i & (Hh * Hh - 1);
        int s = rem >> 10;
        int t = rem & (Hh - 1);
        float v = 0.f;
        if (degS(s) >= degS(t)) v = Wh[l * Hh * Hh + permS(s) * Hh + permS(t)];
        g_Whs[i] = v;
    }
    // hidden biases (permuted)
    for (int i = tid0; i < Ll * Hh; i += stride) {
        int l = i >> 10;
        int s = i & (Hh - 1);
        g_bhs[i] = bh[l * Hh + permS(s)];
    }
    // W0 masked+sorted, stored transposed [D][H] for coalesced rank-1 updates
    for (int i = tid0; i < Dd * Hh; i += stride) {
        int j = i >> 10;          // input column 0..31
        int s = i & (Hh - 1);     // sorted hidden unit
        g_W0sT[i] = (degS(s) >= j) ? W0[permS(s) * Dd + j] : 0.f;
    }
    // output weights masked, cols sorted
    for (int i = tid0; i < 2 * Dd * Hh; i += stride) {
        int o = i >> 10;
        int t = i & (Hh - 1);
        g_Wos[i] = (((o & 31) - 1) >= degS(t)) ? Wout[o * Hh + permS(t)] : 0.f;
    }
}

// pre0 = b0 (x starts at zero); also clear activation scratch (keeps masked-zero
// products finite even on first replay)
__global__ void init_kernel(const float* __restrict__ b0) {
    int stride = gridDim.x * blockDim.x;
    int tid0 = blockIdx.x * blockDim.x + threadIdx.x;
    for (int i = tid0; i < Bb * Hh; i += stride) {
        int s = i & (Hh - 1);
        g_pre0[i] = b0[permS(s)];
        g_a1[i] = 0.f;
        g_a2[i] = 0.f;
    }
}

// ---------------- hidden-layer GEMM: out[:, :h] = relu(A[:, :h] @ W[:h,:h]^T + bias) ----
// A: [B, H] (cols < h valid; beyond-h cols hit exactly-zero masked weights)
// W: [H, H] row-major (out-unit s, in-unit t), block-lower-triangular
// Per-block K-limit exploits triangularity: rows s in this N-tile only have
// nonzero weights for t with deg(t) <= deg(s_max).
#define TM 64
#define TN 64
#define TK 16

__global__ __launch_bounds__(256) void gemm_kernel(const float* __restrict__ A,
                                                   const float* __restrict__ W,
                                                   const float* __restrict__ bias,
                                                   float* __restrict__ out,
                                                   int h, int reluIn) {
    __shared__ float As[TM][TK];
    __shared__ float Bs[TK][TN];

    int m0 = blockIdx.x * TM;
    int n0 = blockIdx.y * TN;

    // triangular K-limit for this N-tile
    int s1 = min(n0 + TN - 1, h - 1);
    int g1 = (s1 < 34) ? 0 : (s1 - 1) / 33;
    int kmax = min(h, 33 * g1 + 34);          // <= 1024 always
    kmax = (kmax + TK - 1) & ~(TK - 1);       // pad to TK; weights are zero in pad

    int tid = (int)threadIdx.x;
    int lr = tid >> 2;            // 0..63: tile row
    int lc = (tid & 3) << 2;      // 0,4,8,12: float4 segment along K
    int tx = tid & 15, ty = tid >> 4;

    float acc[4][4] = {};

    for (int k0 = 0; k0 < kmax; k0 += TK) {
        // A tile: [64 m][16 k], float4 along k
        float4 av = *(const float4*)(A + (size_t)(m0 + lr) * Hh + k0 + lc);
        if (reluIn) {
            av.x = fmaxf(av.x, 0.f); av.y = fmaxf(av.y, 0.f);
            av.z = fmaxf(av.z, 0.f); av.w = fmaxf(av.w, 0.f);
        }
        *(float4*)&As[lr][lc] = av;

        // W tile: rows n0+lr (< 1024 always since grid.y*64 <= 1024), transpose to [k][n]
        float4 wv = *(const float4*)(W + (size_t)(n0 + lr) * Hh + k0 + lc);
        Bs[lc + 0][lr] = wv.x;
        Bs[lc + 1][lr] = wv.y;
        Bs[lc + 2][lr] = wv.z;
        Bs[lc + 3][lr] = wv.w;
        __syncthreads();

#pragma unroll
        for (int kk = 0; kk < TK; kk++) {
            float a0 = As[ty * 4 + 0][kk];
            float a1v = As[ty * 4 + 1][kk];
            float a2v = As[ty * 4 + 2][kk];
            float a3v = As[ty * 4 + 3][kk];
            float4 bv = *(const float4*)&Bs[kk][tx * 4];
            acc[0][0] += a0 * bv.x;  acc[0][1] += a0 * bv.y;
            acc[0][2] += a0 * bv.z;  acc[0][3] += a0 * bv.w;
            acc[1][0] += a1v * bv.x; acc[1][1] += a1v * bv.y;
            acc[1][2] += a1v * bv.z; acc[1][3] += a1v * bv.w;
            acc[2][0] += a2v * bv.x; acc[2][1] += a2v * bv.y;
            acc[2][2] += a2v * bv.z; acc[2][3] += a2v * bv.w;
            acc[3][0] += a3v * bv.x; acc[3][1] += a3v * bv.y;
            acc[3][2] += a3v * bv.z; acc[3][3] += a3v * bv.w;
        }
        __syncthreads();
    }

#pragma unroll
    for (int i = 0; i < 4; i++) {
        int row = m0 + ty * 4 + i;
#pragma unroll
        for (int j = 0; j < 4; j++) {
            int n = n0 + tx * 4 + j;
            if (n < h) out[(size_t)row * Hh + n] = fmaxf(acc[i][j] + bias[n], 0.f);
        }
    }
}

// ---------------- fused output + state update per step ----------------
// mu = Wos[idx]·a2 + bout[idx]; ls = Wos[idx+32]·a2 + bout[idx+32]
// x[:,idx] = z[:,idx]*exp(ls)+mu;  pre0 += W0sT[idx] (rank-1, only s>=h nonzero)
__global__ __launch_bounds__(128) void finish_kernel(const float* __restrict__ z,
                                                     const float* __restrict__ bout,
                                                     float* __restrict__ x,
                                                     int idx, int h) {
    int r = blockIdx.x;
    int t = (int)threadIdx.x;
    const float* arow = g_a2 + (size_t)r * Hh;
    const float* wmu = g_Wos + (size_t)idx * Hh;
    const float* wls = g_Wos + (size_t)(idx + Dd) * Hh;

    float smu = 0.f, sls = 0.f;
    for (int c = t; c < h; c += 128) {
        float av = arow[c];
        smu += av * wmu[c];
        sls += av * wls[c];
    }
#pragma unroll
    for (int off = 16; off; off >>= 1) {
        smu += __shfl_down_sync(0xffffffffu, smu, off);
        sls += __shfl_down_sync(0xffffffffu, sls, off);
    }
    __shared__ float rmu[4], rls[4];
    __shared__ float s_xi;
    if ((t & 31) == 0) { rmu[t >> 5] = smu; rls[t >> 5] = sls; }
    __syncthreads();
    if (t == 0) {
        float mu = rmu[0] + rmu[1] + rmu[2] + rmu[3] + bout[idx];
        float ls = rls[0] + rls[1] + rls[2] + rls[3] + bout[idx + Dd];
        float xi = z[(size_t)r * Dd + idx] * expf(ls) + mu;
        x[(size_t)r * Dd + idx] = xi;
        s_xi = xi;
    }
    __syncthreads();
    float xi = s_xi;
    const float* w0col = g_W0sT + idx * Hh;
    float* prow = g_pre0 + (size_t)r * Hh;
    // W0sT[idx][s] is zero for s < h (deg < idx), so only update the suffix
    for (int s = h + t; s < Hh; s += 128) prow[s] += w0col[s] * xi;
}

// ---------------- launch ----------------
extern "C" void kernel_launch(void* const* d_in, const int* in_sizes, int n_in,
                              void* d_out, int out_size) {
    const float* z    = (const float*)d_in[0];
    const float* W0   = (const float*)d_in[1];
    const float* b0   = (const float*)d_in[2];
    const float* Wh   = (const float*)d_in[3];
    const float* bh   = (const float*)d_in[4];
    const float* Wout = (const float*)d_in[5];
    const float* bout = (const float*)d_in[6];
    float* x = (float*)d_out;

    prep_kernel<<<1024, 256>>>(W0, Wh, bh, Wout);
    init_kernel<<<1024, 256>>>(b0);

    float *pre0, *a1, *a2, *Whs, *bhs;
    cudaGetSymbolAddress((void**)&pre0, g_pre0);
    cudaGetSymbolAddress((void**)&a1, g_a1);
    cudaGetSymbolAddress((void**)&a2, g_a2);
    cudaGetSymbolAddress((void**)&Whs, g_Whs);
    cudaGetSymbolAddress((void**)&bhs, g_bhs);

    for (int idx = 0; idx < Dd; idx++) {
        int h = prefixH(idx);
        if (h > 0) {
            dim3 grid(Bb / TM, (h + TN - 1) / TN);
            // layer 1: input relu(pre0) applied on load
            gemm_kernel<<<grid, 256>>>(pre0, Whs, bhs, a1, h, 1);
            // layer 2: a1 already post-relu
            gemm_kernel<<<grid, 256>>>(a1, Whs + Hh * Hh, bhs + Hh, a2, h, 0);
        }
        finish_kernel<<<Bb, 128>>>(z, bout, x, idx, h);
    }
}

// round 2
// speedup vs baseline: 1.3182x; 1.3182x over previous
#include <cuda_runtime.h>
#include <math.h>
#include <stdint.h>

// Problem constants
#define Dd 32
#define Hh 1024
#define Ll 2
#define Bb 4096

// ---------------- device scratch (static, no allocation) ----------------
__device__ float g_pre0[Bb * Hh];          // layer-0 pre-activations (fp32), incrementally maintained
__device__ float g_a1[Bb * Hh];            // hidden layer 1 output (post-relu, fp32)
__device__ float g_a2[Bb * Hh];            // hidden layer 2 output (post-relu, fp32)
__device__ float g_Whs_hi[Ll * Hh * Hh];   // masked, degree-sorted hidden weights, tf32 hi part
__device__ float g_Whs_lo[Ll * Hh * Hh];   // tf32 lo part (residual)
__device__ float g_bhs[Ll * Hh];           // permuted hidden biases
__device__ float g_W0sT[Dd * Hh];          // masked, sorted W0, TRANSPOSED: [D][H]
__device__ float g_Wos[2 * Dd * Hh];       // masked output weights, sorted cols (fp32)

// Degree-sorted permutation. Hidden degree of original unit i is i % 31.
__device__ __forceinline__ int permS(int s) {
    return (s < 34) ? 31 * s : ((s - 1) / 33) + 31 * ((s - 1) % 33);
}
__device__ __forceinline__ int degS(int s) {
    return (s < 34) ? 0 : (s - 1) / 33;
}

// prefix size at step idx: number of hidden units with degree <= idx-1
static inline int prefixH(int idx) { return (idx == 0) ? 0 : (33 * idx + 1); }

// tf32 round (RNA) -> returns fp32 bit pattern with truncated mantissa
__device__ __forceinline__ float f2tf32f(float x) {
    uint32_t r;
    asm("cvt.rna.tf32.f32 %0, %1;" : "=r"(r) : "f"(x));
    return __uint_as_float(r);
}

// ---------------- weight pre-transform (masked + degree-sorted + tf32 split) ----
__global__ void prep_kernel(const float* __restrict__ W0,
                            const float* __restrict__ Wh,
                            const float* __restrict__ bh,
                            const float* __restrict__ Wout) {
    int stride = gridDim.x * blockDim.x;
    int tid0 = blockIdx.x * blockDim.x + threadIdx.x;

    for (int i = tid0; i < Ll * Hh * Hh; i += stride) {
        int l = i >> 20;
        int rem = i & (Hh * Hh - 1);
        int s = rem >> 10;
        int t = rem & (Hh - 1);
        float v = 0.f;
        if (degS(s) >= degS(t)) v = Wh[l * Hh * Hh + permS(s) * Hh + permS(t)];
        float hi = f2tf32f(v);
        g_Whs_hi[i] = hi;
        g_Whs_lo[i] = f2tf32f(v - hi);
    }
    for (int i = tid0; i < Ll * Hh; i += stride) {
        int l = i >> 10;
        int s = i & (Hh - 1);
        g_bhs[i] = bh[l * Hh + permS(s)];
    }
    for (int i = tid0; i < Dd * Hh; i += stride) {
        int j = i >> 10;
        int s = i & (Hh - 1);
        g_W0sT[i] = (degS(s) >= j) ? W0[permS(s) * Dd + j] : 0.f;
    }
    for (int i = tid0; i < 2 * Dd * Hh; i += stride) {
        int o = i >> 10;
        int t = i & (Hh - 1);
        g_Wos[i] = (((o & 31) - 1) >= degS(t)) ? Wout[o * Hh + permS(t)] : 0.f;
    }
}

__global__ void init_kernel(const float* __restrict__ b0) {
    int stride = gridDim.x * blockDim.x;
    int tid0 = blockIdx.x * blockDim.x + threadIdx.x;
    for (int i = tid0; i < Bb * Hh; i += stride) {
        int s = i & (Hh - 1);
        g_pre0[i] = b0[permS(s)];
        g_a1[i] = 0.f;
        g_a2[i] = 0.f;
    }
}

// ---------------- tf32 tensor-core GEMM (3-pass error-compensated) --------------
// out[:, n<h] = relu( A[:, :kmax] @ W[:h,:kmax]^T + bias )
// A fp32 [B,1024]; W split hi/lo [1024,1024]. Block tile 128x64, BK=32.
// 8 warps: wm = wid&3 (M), wn = wid>>2 (N). Warp tile 32x32 (2 m16 x 4 n8).
#define BM 128
#define BN 64
#define BK 32
#define SPAD 36   // smem row stride (floats): +4 pad -> conflict-free frag LDS

__device__ __forceinline__ void mma_tf32(float c[4], const uint32_t a[4], const uint32_t b[2]) {
    asm volatile(
        "mma.sync.aligned.m16n8k8.row.col.f32.tf32.tf32.f32 "
        "{%0,%1,%2,%3}, {%4,%5,%6,%7}, {%8,%9}, {%0,%1,%2,%3};\n"
        : "+f"(c[0]), "+f"(c[1]), "+f"(c[2]), "+f"(c[3])
        : "r"(a[0]), "r"(a[1]), "r"(a[2]), "r"(a[3]), "r"(b[0]), "r"(b[1]));
}

__global__ __launch_bounds__(256) void gemm_tc(const float* __restrict__ A,
                                               const float* __restrict__ Whi,
                                               const float* __restrict__ Wlo,
                                               const float* __restrict__ bias,
                                               float* __restrict__ out,
                                               int h, int reluIn) {
    extern __shared__ float sm[];
    float* As_hi = sm;                       // [BM][SPAD]
    float* As_lo = As_hi + BM * SPAD;
    float* Bs_hi = As_lo + BM * SPAD;        // [BN][SPAD]
    float* Bs_lo = Bs_hi + BN * SPAD;

    const int m0 = blockIdx.x * BM;
    const int n0 = blockIdx.y * BN;

    // triangular K-limit for this N-tile (weights beyond are exactly zero)
    int s1 = min(n0 + BN - 1, h - 1);
    int g1 = (s1 < 34) ? 0 : (s1 - 1) / 33;
    int kmax = min(h, 33 * g1 + 34);
    kmax = (kmax + BK - 1) & ~(BK - 1);

    const int tid = (int)threadIdx.x;
    const int lane = tid & 31;
    const int wid = tid >> 5;
    const int wm = wid & 3;       // warp M index (0..3)
    const int wn = wid >> 2;      // warp N index (0..1)
    const int g = lane >> 2;      // group 0..7
    const int tg = lane & 3;      // thread-in-group 0..3

    float c[2][4][4];
#pragma unroll
    for (int mi = 0; mi < 2; mi++)
#pragma unroll
        for (int ni = 0; ni < 4; ni++)
#pragma unroll
            for (int q = 0; q < 4; q++) c[mi][ni][q] = 0.f;

    for (int k0 = 0; k0 < kmax; k0 += BK) {
        // ---- stage A tile: BM x BK, split to tf32 hi/lo (relu for layer 1) ----
#pragma unroll
        for (int i = 0; i < 4; i++) {
            int idx = tid + i * 256;          // 0..1023
            int r = idx >> 3;                 // 0..127
            int cs = (idx & 7) << 2;          // 0,4,..,28
            float4 av = *(const float4*)(A + (size_t)(m0 + r) * Hh + k0 + cs);
            if (reluIn) {
                av.x = fmaxf(av.x, 0.f); av.y = fmaxf(av.y, 0.f);
                av.z = fmaxf(av.z, 0.f); av.w = fmaxf(av.w, 0.f);
            }
            float4 hv, lv;
            hv.x = f2tf32f(av.x); lv.x = f2tf32f(av.x - hv.x);
            hv.y = f2tf32f(av.y); lv.y = f2tf32f(av.y - hv.y);
            hv.z = f2tf32f(av.z); lv.z = f2tf32f(av.z - hv.z);
            hv.w = f2tf32f(av.w); lv.w = f2tf32f(av.w - hv.w);
            *(float4*)(As_hi + r * SPAD + cs) = hv;
            *(float4*)(As_lo + r * SPAD + cs) = lv;
        }
        // ---- stage B tile: BN x BK (pre-split weights) ----
#pragma unroll
        for (int i = 0; i < 2; i++) {
            int idx = tid + i * 256;          // 0..511
            int r = idx >> 3;                 // 0..63
            int cs = (idx & 7) << 2;
            size_t go = (size_t)(n0 + r) * Hh + k0 + cs;
            *(float4*)(Bs_hi + r * SPAD + cs) = *(const float4*)(Whi + go);
            *(float4*)(Bs_lo + r * SPAD + cs) = *(const float4*)(Wlo + go);
        }
        __syncthreads();

#pragma unroll
        for (int ks = 0; ks < BK; ks += 8) {
            uint32_t ah[2][4], al[2][4], bh[4][2], bl[4][2];
#pragma unroll
            for (int mi = 0; mi < 2; mi++) {
                int rb = wm * 32 + mi * 16;
                ah[mi][0] = __float_as_uint(As_hi[(rb + g) * SPAD + ks + tg]);
                ah[mi][1] = __float_as_uint(As_hi[(rb + g + 8) * SPAD + ks + tg]);
                ah[mi][2] = __float_as_uint(As_hi[(rb + g) * SPAD + ks + tg + 4]);
                ah[mi][3] = __float_as_uint(As_hi[(rb + g + 8) * SPAD + ks + tg + 4]);
                al[mi][0] = __float_as_uint(As_lo[(rb + g) * SPAD + ks + tg]);
                al[mi][1] = __float_as_uint(As_lo[(rb + g + 8) * SPAD + ks + tg]);
                al[mi][2] = __float_as_uint(As_lo[(rb + g) * SPAD + ks + tg + 4]);
                al[mi][3] = __float_as_uint(As_lo[(rb + g + 8) * SPAD + ks + tg + 4]);
            }
#pragma unroll
            for (int ni = 0; ni < 4; ni++) {
                int cb = wn * 32 + ni * 8;
                bh[ni][0] = __float_as_uint(Bs_hi[(cb + g) * SPAD + ks + tg]);
                bh[ni][1] = __float_as_uint(Bs_hi[(cb + g) * SPAD + ks + tg + 4]);
                bl[ni][0] = __float_as_uint(Bs_lo[(cb + g) * SPAD + ks + tg]);
                bl[ni][1] = __float_as_uint(Bs_lo[(cb + g) * SPAD + ks + tg + 4]);
            }
#pragma unroll
            for (int mi = 0; mi < 2; mi++)
#pragma unroll
                for (int ni = 0; ni < 4; ni++) {
                    mma_tf32(c[mi][ni], ah[mi], bh[ni]);
                    mma_tf32(c[mi][ni], al[mi], bh[ni]);
                    mma_tf32(c[mi][ni], ah[mi], bl[ni]);
                }
        }
        __syncthreads();
    }

    // ---- epilogue: bias + relu, store cols < h ----
#pragma unroll
    for (int mi = 0; mi < 2; mi++) {
        int r0 = m0 + wm * 32 + mi * 16 + g;
#pragma unroll
        for (int ni = 0; ni < 4; ni++) {
            int col = n0 + wn * 32 + ni * 8 + tg * 2;
            if (col < h) {
                float b0v = bias[col];
                out[(size_t)r0 * Hh + col] = fmaxf(c[mi][ni][0] + b0v, 0.f);
                out[(size_t)(r0 + 8) * Hh + col] = fmaxf(c[mi][ni][2] + b0v, 0.f);
            }
            if (col + 1 < h) {
                float b1v = bias[col + 1];
                out[(size_t)r0 * Hh + col + 1] = fmaxf(c[mi][ni][1] + b1v, 0.f);
                out[(size_t)(r0 + 8) * Hh + col + 1] = fmaxf(c[mi][ni][3] + b1v, 0.f);
            }
        }
    }
}

// ---------------- fused output + state update per step ----------------
__global__ __launch_bounds__(128) void finish_kernel(const float* __restrict__ z,
                                                     const float* __restrict__ bout,
                                                     float* __restrict__ x,
                                                     int idx, int h) {
    int r = blockIdx.x;
    int t = (int)threadIdx.x;
    const float* arow = g_a2 + (size_t)r * Hh;
    const float* wmu = g_Wos + (size_t)idx * Hh;
    const float* wls = g_Wos + (size_t)(idx + Dd) * Hh;

    float smu = 0.f, sls = 0.f;
    for (int ccol = t; ccol < h; ccol += 128) {
        float av = arow[ccol];
        smu += av * wmu[ccol];
        sls += av * wls[ccol];
    }
#pragma unroll
    for (int off = 16; off; off >>= 1) {
        smu += __shfl_down_sync(0xffffffffu, smu, off);
        sls += __shfl_down_sync(0xffffffffu, sls, off);
    }
    __shared__ float rmu[4], rls[4];
    __shared__ float s_xi;
    if ((t & 31) == 0) { rmu[t >> 5] = smu; rls[t >> 5] = sls; }
    __syncthreads();
    if (t == 0) {
        float mu = rmu[0] + rmu[1] + rmu[2] + rmu[3] + bout[idx];
        float ls = rls[0] + rls[1] + rls[2] + rls[3] + bout[idx + Dd];
        float xi = z[(size_t)r * Dd + idx] * expf(ls) + mu;
        x[(size_t)r * Dd + idx] = xi;
        s_xi = xi;
    }
    __syncthreads();
    float xi = s_xi;
    const float* w0col = g_W0sT + idx * Hh;
    float* prow = g_pre0 + (size_t)r * Hh;
    for (int s = h + t; s < Hh; s += 128) prow[s] += w0col[s] * xi;
}

// ---------------- launch ----------------
extern "C" void kernel_launch(void* const* d_in, const int* in_sizes, int n_in,
                              void* d_out, int out_size) {
    const float* z    = (const float*)d_in[0];
    const float* W0   = (const float*)d_in[1];
    const float* b0   = (const float*)d_in[2];
    const float* Wh   = (const float*)d_in[3];
    const float* bh   = (const float*)d_in[4];
    const float* Wout = (const float*)d_in[5];
    const float* bout = (const float*)d_in[6];
    float* x = (float*)d_out;

    const int smemBytes = (2 * BM * SPAD + 2 * BN * SPAD) * (int)sizeof(float); // 55296
    static int attrSet = 0;
    if (!attrSet) {
        cudaFuncSetAttribute(gemm_tc, cudaFuncAttributeMaxDynamicSharedMemorySize, smemBytes);
        attrSet = 1;
    }

    prep_kernel<<<1024, 256>>>(W0, Wh, bh, Wout);
    init_kernel<<<1024, 256>>>(b0);

    float *pre0, *a1, *a2, *Whi, *Wlo, *bhs;
    cudaGetSymbolAddress((void**)&pre0, g_pre0);
    cudaGetSymbolAddress((void**)&a1, g_a1);
    cudaGetSymbolAddress((void**)&a2, g_a2);
    cudaGetSymbolAddress((void**)&Whi, g_Whs_hi);
    cudaGetSymbolAddress((void**)&Wlo, g_Whs_lo);
    cudaGetSymbolAddress((void**)&bhs, g_bhs);

    for (int idx = 0; idx < Dd; idx++) {
        int h = prefixH(idx);
        if (h > 0) {
            dim3 grid(Bb / BM, (h + BN - 1) / BN);
            gemm_tc<<<grid, 256, smemBytes>>>(pre0, Whi, Wlo, bhs, a1, h, 1);
            gemm_tc<<<grid, 256, smemBytes>>>(a1, Whi + Hh * Hh, Wlo + Hh * Hh,
                                              bhs + Hh, a2, h, 0);
        }
        finish_kernel<<<Bb, 128>>>(z, bout, x, idx, h);
    }
}

// round 3
// speedup vs baseline: 1.8556x; 1.4077x over previous
#include <cuda_runtime.h>
#include <cuda_bf16.h>
#include <math.h>
#include <stdint.h>

// Problem constants
#define Dd 32
#define Hh 1024
#define Ll 2
#define Bb 4096

// ---------------- device scratch (static, no allocation) ----------------
__device__ float g_pre0[Bb * Hh];                  // layer-0 pre-activations (fp32)
__device__ float g_a1[Bb * Hh];                    // hidden layer 1 output (post-relu)
__device__ float g_a2[Bb * Hh];                    // hidden layer 2 output (post-relu)
__device__ __nv_bfloat16 g_Wh_hi[Ll * Hh * Hh];    // masked, sorted hidden weights, bf16 hi
__device__ __nv_bfloat16 g_Wh_lo[Ll * Hh * Hh];    // bf16 lo residual
__device__ float g_bhs[Ll * Hh];                   // permuted hidden biases
__device__ float g_W0sT[Dd * Hh];                  // masked, sorted W0, transposed [D][H]
__device__ float g_Wos[2 * Dd * Hh];               // masked output weights, sorted cols

// Degree-sorted permutation. Hidden degree of original unit i is i % 31.
__device__ __forceinline__ int permS(int s) {
    return (s < 34) ? 31 * s : ((s - 1) / 33) + 31 * ((s - 1) % 33);
}
__device__ __forceinline__ int degS(int s) {
    return (s < 34) ? 0 : (s - 1) / 33;
}
static inline int prefixH(int idx) { return (idx == 0) ? 0 : (33 * idx + 1); }

// ---------------- weight pre-transform (masked + sorted + bf16 split) -----------
__global__ void prep_kernel(const float* __restrict__ W0,
                            const float* __restrict__ Wh,
                            const float* __restrict__ bh,
                            const float* __restrict__ Wout) {
    int stride = gridDim.x * blockDim.x;
    int tid0 = blockIdx.x * blockDim.x + threadIdx.x;

    for (int i = tid0; i < Ll * Hh * Hh; i += stride) {
        int l = i >> 20;
        int rem = i & (Hh * Hh - 1);
        int s = rem >> 10;
        int t = rem & (Hh - 1);
        float v = 0.f;
        if (degS(s) >= degS(t)) v = Wh[l * Hh * Hh + permS(s) * Hh + permS(t)];
        __nv_bfloat16 hi = __float2bfloat16_rn(v);
        g_Wh_hi[i] = hi;
        g_Wh_lo[i] = __float2bfloat16_rn(v - __bfloat162float(hi));
    }
    for (int i = tid0; i < Ll * Hh; i += stride) {
        int l = i >> 10;
        int s = i & (Hh - 1);
        g_bhs[i] = bh[l * Hh + permS(s)];
    }
    for (int i = tid0; i < Dd * Hh; i += stride) {
        int j = i >> 10;
        int s = i & (Hh - 1);
        g_W0sT[i] = (degS(s) >= j) ? W0[permS(s) * Dd + j] : 0.f;
    }
    for (int i = tid0; i < 2 * Dd * Hh; i += stride) {
        int o = i >> 10;
        int t = i & (Hh - 1);
        g_Wos[i] = (((o & 31) - 1) >= degS(t)) ? Wout[o * Hh + permS(t)] : 0.f;
    }
}

__global__ void init_kernel(const float* __restrict__ b0) {
    int stride = gridDim.x * blockDim.x;
    int tid0 = blockIdx.x * blockDim.x + threadIdx.x;
    for (int i = tid0; i < Bb * Hh; i += stride) {
        int s = i & (Hh - 1);
        g_pre0[i] = b0[permS(s)];
        g_a1[i] = 0.f;
        g_a2[i] = 0.f;
    }
}

// ---------------- bf16 tensor-core GEMM (3-pass error-compensated) --------------
// out[:, n<h] = relu( A @ W^T + bias ), W block-lower-triangular (per-tile K limit).
// Block tile 128x64, BK=32. 8 warps: warp tile 32x32 (2 x m16, 4 x n8), k16 MMA.
#define BM 128
#define BN 64
#define BK 32
#define APAD 40   // bf16 elements per smem row (80 B) -> conflict-free ldmatrix

__device__ __forceinline__ uint32_t smem_u32(const void* p) {
    return (uint32_t)__cvta_generic_to_shared(p);
}
__device__ __forceinline__ void ldsm4(uint32_t& r0, uint32_t& r1, uint32_t& r2,
                                      uint32_t& r3, uint32_t addr) {
    asm volatile("ldmatrix.sync.aligned.m8n8.x4.shared.b16 {%0,%1,%2,%3}, [%4];\n"
                 : "=r"(r0), "=r"(r1), "=r"(r2), "=r"(r3) : "r"(addr));
}
__device__ __forceinline__ void mma_bf16(float c[4], const uint32_t a[4], const uint32_t b[2]) {
    asm volatile(
        "mma.sync.aligned.m16n8k16.row.col.f32.bf16.bf16.f32 "
        "{%0,%1,%2,%3}, {%4,%5,%6,%7}, {%8,%9}, {%0,%1,%2,%3};\n"
        : "+f"(c[0]), "+f"(c[1]), "+f"(c[2]), "+f"(c[3])
        : "r"(a[0]), "r"(a[1]), "r"(a[2]), "r"(a[3]), "r"(b[0]), "r"(b[1]));
}
__device__ __forceinline__ uint32_t splitpack_hi(float x, float y, float& rx, float& ry) {
    __nv_bfloat16 hx = __float2bfloat16_rn(x);
    __nv_bfloat16 hy = __float2bfloat16_rn(y);
    rx = x - __bfloat162float(hx);
    ry = y - __bfloat162float(hy);
    __nv_bfloat162 p; p.x = hx; p.y = hy;
    return *(uint32_t*)&p;
}
__device__ __forceinline__ uint32_t pack_lo(float rx, float ry) {
    __nv_bfloat162 p;
    p.x = __float2bfloat16_rn(rx);
    p.y = __float2bfloat16_rn(ry);
    return *(uint32_t*)&p;
}

__global__ __launch_bounds__(256) void gemm_tc(const float* __restrict__ A,
                                               const __nv_bfloat16* __restrict__ Whi,
                                               const __nv_bfloat16* __restrict__ Wlo,
                                               const float* __restrict__ bias,
                                               float* __restrict__ out,
                                               int h, int reluIn) {
    __shared__ __nv_bfloat16 As_hi[BM * APAD];
    __shared__ __nv_bfloat16 As_lo[BM * APAD];
    __shared__ __nv_bfloat16 Bs_hi[BN * APAD];
    __shared__ __nv_bfloat16 Bs_lo[BN * APAD];

    const int m0 = blockIdx.x * BM;
    const int n0 = blockIdx.y * BN;

    // triangular K-limit for this N-tile
    int s1 = min(n0 + BN - 1, h - 1);
    int g1 = (s1 < 34) ? 0 : (s1 - 1) / 33;
    int kmax = min(h, 33 * g1 + 34);
    kmax = (kmax + BK - 1) & ~(BK - 1);

    const int tid = (int)threadIdx.x;
    const int lane = tid & 31;
    const int wid = tid >> 5;
    const int wm = wid & 3;       // warp M (0..3), 32 rows each
    const int wn = wid >> 2;      // warp N (0..1), 32 cols each
    const int g = lane >> 2;
    const int tg = lane & 3;

    const uint32_t sAhi = smem_u32(As_hi);
    const uint32_t sAlo = smem_u32(As_lo);
    const uint32_t sBhi = smem_u32(Bs_hi);
    const uint32_t sBlo = smem_u32(Bs_lo);

    float c[2][4][4];
#pragma unroll
    for (int mi = 0; mi < 2; mi++)
#pragma unroll
        for (int ni = 0; ni < 4; ni++)
#pragma unroll
            for (int q = 0; q < 4; q++) c[mi][ni][q] = 0.f;

    // ldmatrix lane address components
    const int lrow = lane & 15;
    const int lkof = (lane >> 4) << 3;

    for (int k0 = 0; k0 < kmax; k0 += BK) {
        // ---- stage A tile: BM x BK fp32 -> bf16 hi/lo ----
#pragma unroll
        for (int i = 0; i < 4; i++) {
            int idx = tid + i * 256;          // 0..1023
            int r = idx >> 3;                 // 0..127
            int cs = (idx & 7) << 2;          // 0,4,...,28
            float4 av = *(const float4*)(A + (size_t)(m0 + r) * Hh + k0 + cs);
            if (reluIn) {
                av.x = fmaxf(av.x, 0.f); av.y = fmaxf(av.y, 0.f);
                av.z = fmaxf(av.z, 0.f); av.w = fmaxf(av.w, 0.f);
            }
            float rx, ry, rz, rw;
            uint32_t h01 = splitpack_hi(av.x, av.y, rx, ry);
            uint32_t h23 = splitpack_hi(av.z, av.w, rz, rw);
            uint32_t l01 = pack_lo(rx, ry);
            uint32_t l23 = pack_lo(rz, rw);
            uint2* ph = (uint2*)(As_hi + r * APAD + cs);
            uint2* pl = (uint2*)(As_lo + r * APAD + cs);
            *ph = make_uint2(h01, h23);
            *pl = make_uint2(l01, l23);
        }
        // ---- stage B tile: BN x BK pre-split bf16 ----
#pragma unroll
        for (int i = 0; i < 2; i++) {
            int idx = tid + i * 256;          // 0..511
            int r = idx >> 3;                 // 0..63
            int cs = (idx & 7) << 2;          // bf16 col (4 at a time)
            size_t go = (size_t)(n0 + r) * Hh + k0 + cs;
            *(uint2*)(Bs_hi + r * APAD + cs) = *(const uint2*)(Whi + go);
            *(uint2*)(Bs_lo + r * APAD + cs) = *(const uint2*)(Wlo + go);
        }
        __syncthreads();

#pragma unroll
        for (int kst = 0; kst < 2; kst++) {
            const int ks = kst * 16;
            uint32_t ah[2][4], al[2][4];
#pragma unroll
            for (int mi = 0; mi < 2; mi++) {
                int row = wm * 32 + mi * 16 + lrow;
                uint32_t off = (uint32_t)(row * APAD + ks + lkof) * 2u;
                ldsm4(ah[mi][0], ah[mi][1], ah[mi][2], ah[mi][3], sAhi + off);
                ldsm4(al[mi][0], al[mi][1], al[mi][2], al[mi][3], sAlo + off);
            }
            uint32_t bh[4][2], bl[4][2];
#pragma unroll
            for (int nj = 0; nj < 2; nj++) {
                int nrow = wn * 32 + nj * 16 + lrow;
                uint32_t off = (uint32_t)(nrow * APAD + ks + lkof) * 2u;
                uint32_t t0, t1, t2, t3;
                ldsm4(t0, t1, t2, t3, sBhi + off);
                bh[nj * 2][0] = t0; bh[nj * 2 + 1][0] = t1;
                bh[nj * 2][1] = t2; bh[nj * 2 + 1][1] = t3;
                ldsm4(t0, t1, t2, t3, sBlo + off);
                bl[nj * 2][0] = t0; bl[nj * 2 + 1][0] = t1;
                bl[nj * 2][1] = t2; bl[nj * 2 + 1][1] = t3;
            }
#pragma unroll
            for (int mi = 0; mi < 2; mi++)
#pragma unroll
                for (int ni = 0; ni < 4; ni++) {
                    mma_bf16(c[mi][ni], ah[mi], bh[ni]);
                    mma_bf16(c[mi][ni], al[mi], bh[ni]);
                    mma_bf16(c[mi][ni], ah[mi], bl[ni]);
                }
        }
        __syncthreads();
    }

    // ---- epilogue: bias + relu, store cols < h ----
#pragma unroll
    for (int mi = 0; mi < 2; mi++) {
        int r0 = m0 + wm * 32 + mi * 16 + g;
#pragma unroll
        for (int ni = 0; ni < 4; ni++) {
            int col = n0 + wn * 32 + ni * 8 + tg * 2;
            if (col < h) {
                float b0v = bias[col];
                out[(size_t)r0 * Hh + col] = fmaxf(c[mi][ni][0] + b0v, 0.f);
                out[(size_t)(r0 + 8) * Hh + col] = fmaxf(c[mi][ni][2] + b0v, 0.f);
            }
            if (col + 1 < h) {
                float b1v = bias[col + 1];
                out[(size_t)r0 * Hh + col + 1] = fmaxf(c[mi][ni][1] + b1v, 0.f);
                out[(size_t)(r0 + 8) * Hh + col + 1] = fmaxf(c[mi][ni][3] + b1v, 0.f);
            }
        }
    }
}

// ---------------- fused output + state update per step ----------------
__global__ __launch_bounds__(128) void finish_kernel(const float* __restrict__ z,
                                                     const float* __restrict__ bout,
                                                     float* __restrict__ x,
                                                     int idx, int h) {
    int r = blockIdx.x;
    int t = (int)threadIdx.x;
    const float* arow = g_a2 + (size_t)r * Hh;
    const float* wmu = g_Wos + (size_t)idx * Hh;
    const float* wls = g_Wos + (size_t)(idx + Dd) * Hh;

    float smu = 0.f, sls = 0.f;
    for (int ccol = t; ccol < h; ccol += 128) {
        float av = arow[ccol];
        smu += av * wmu[ccol];
        sls += av * wls[ccol];
    }
#pragma unroll
    for (int off = 16; off; off >>= 1) {
        smu += __shfl_down_sync(0xffffffffu, smu, off);
        sls += __shfl_down_sync(0xffffffffu, sls, off);
    }
    __shared__ float rmu[4], rls[4];
    __shared__ float s_xi;
    if ((t & 31) == 0) { rmu[t >> 5] = smu; rls[t >> 5] = sls; }
    __syncthreads();
    if (t == 0) {
        float mu = rmu[0] + rmu[1] + rmu[2] + rmu[3] + bout[idx];
        float ls = rls[0] + rls[1] + rls[2] + rls[3] + bout[idx + Dd];
        float xi = z[(size_t)r * Dd + idx] * expf(ls) + mu;
        x[(size_t)r * Dd + idx] = xi;
        s_xi = xi;
    }
    __syncthreads();
    float xi = s_xi;
    const float* w0col = g_W0sT + idx * Hh;
    float* prow = g_pre0 + (size_t)r * Hh;
    for (int s = h + t; s < Hh; s += 128) prow[s] += w0col[s] * xi;
}

// ---------------- launch ----------------
extern "C" void kernel_launch(void* const* d_in, const int* in_sizes, int n_in,
                              void* d_out, int out_size) {
    const float* z    = (const float*)d_in[0];
    const float* W0   = (const float*)d_in[1];
    const float* b0   = (const float*)d_in[2];
    const float* Wh   = (const float*)d_in[3];
    const float* bh   = (const float*)d_in[4];
    const float* Wout = (const float*)d_in[5];
    const float* bout = (const float*)d_in[6];
    float* x = (float*)d_out;

    prep_kernel<<<1024, 256>>>(W0, Wh, bh, Wout);
    init_kernel<<<1024, 256>>>(b0);

    float *pre0, *a1, *a2, *bhs;
    __nv_bfloat16 *Whi, *Wlo;
    cudaGetSymbolAddress((void**)&pre0, g_pre0);
    cudaGetSymbolAddress((void**)&a1, g_a1);
    cudaGetSymbolAddress((void**)&a2, g_a2);
    cudaGetSymbolAddress((void**)&Whi, g_Wh_hi);
    cudaGetSymbolAddress((void**)&Wlo, g_Wh_lo);
    cudaGetSymbolAddress((void**)&bhs, g_bhs);

    for (int idx = 0; idx < Dd; idx++) {
        int h = prefixH(idx);
        if (h > 0) {
            dim3 grid(Bb / BM, (h + BN - 1) / BN);
            gemm_tc<<<grid, 256>>>(pre0, Whi, Wlo, bhs, a1, h, 1);
            gemm_tc<<<grid, 256>>>(a1, Whi + Hh * Hh, Wlo + Hh * Hh,
                                   bhs + Hh, a2, h, 0);
        }
        finish_kernel<<<Bb, 128>>>(z, bout, x, idx, h);
    }
}